// round 1
// baseline (speedup 1.0000x reference)
#include <cuda_runtime.h>

#define Bb 2
#define Ss 2048
#define Ee 1024
#define Hh 16
#define Hd 64

// Scratch (allocation-free rule: __device__ globals)
__device__ float g_Q1[Bb * Ss * Hd];      // head-1 Q, (b, 2048, 64) contiguous
__device__ float g_K1[Bb * Ss * Hd];      // head-1 K
__device__ float g_V[Bb * Ss * Ee];       // full V projection, flat (b, h, s, d)
__device__ float g_attn[Bb * Ss * Ee];    // attn_out, flat (b, h, s, d)

// ---------------------------------------------------------------------------
// Generic NT GEMM: C[m,n] = sum_k A[m,k] * B[n,k] + bias[n]
// A: (M,K) row-major (per-batch stride sA), B: (N,K) row-major (shared),
// C: (M,N) row-major (per-batch stride sC). M,N multiples of 64, K of 16.
// BM=BN=64, BK=16, 256 threads, 4x4 per-thread tile.
// ---------------------------------------------------------------------------
__global__ void gemm_nt(const float* __restrict__ A, const float* __restrict__ B,
                        const float* __restrict__ bias, float* __restrict__ C,
                        int M, int N, int K, long sA, long sC)
{
    __shared__ float As[16][64];   // [k][m]
    __shared__ float Bs[16][64];   // [k][n]
    A += (long)blockIdx.z * sA;
    C += (long)blockIdx.z * sC;
    const int m0 = blockIdx.y * 64, n0 = blockIdx.x * 64;
    const int tid = threadIdx.x;
    const int tx = tid & 15, ty = tid >> 4;
    const int lr = tid >> 2, lc = (tid & 3) * 4;   // loader: row 0..63, k-col 0..12
    float acc[4][4] = {};

    for (int k0 = 0; k0 < K; k0 += 16) {
        float4 av = *(const float4*)&A[(long)(m0 + lr) * K + k0 + lc];
        float4 bv = *(const float4*)&B[(long)(n0 + lr) * K + k0 + lc];
        As[lc + 0][lr] = av.x; As[lc + 1][lr] = av.y; As[lc + 2][lr] = av.z; As[lc + 3][lr] = av.w;
        Bs[lc + 0][lr] = bv.x; Bs[lc + 1][lr] = bv.y; Bs[lc + 2][lr] = bv.z; Bs[lc + 3][lr] = bv.w;
        __syncthreads();
        #pragma unroll
        for (int k = 0; k < 16; k++) {
            float4 a4 = *(const float4*)&As[k][ty * 4];
            float4 b4 = *(const float4*)&Bs[k][tx * 4];
            float ar[4] = {a4.x, a4.y, a4.z, a4.w};
            float br[4] = {b4.x, b4.y, b4.z, b4.w};
            #pragma unroll
            for (int i = 0; i < 4; i++)
                #pragma unroll
                for (int j = 0; j < 4; j++)
                    acc[i][j] += ar[i] * br[j];
        }
        __syncthreads();
    }

    #pragma unroll
    for (int i = 0; i < 4; i++) {
        const int m = m0 + ty * 4 + i;
        #pragma unroll
        for (int j = 0; j < 4; j++) {
            const int n = n0 + tx * 4 + j;
            float v = acc[i][j];
            if (bias) v += bias[n];
            C[(long)m * N + n] = v;
        }
    }
}

// ---------------------------------------------------------------------------
// Head-1 attention scores with ALiBi bias, written (pre-softmax) into P.
// P[b, q, k] = 0.125 * dot(Q1[b,q,:], K1[b,k,:]) - slope1 * |q - k|
// ---------------------------------------------------------------------------
__global__ void scores_kernel(const float* __restrict__ slopes, float* __restrict__ P)
{
    __shared__ float Qs[16][64];
    __shared__ float Ks[16][64];
    const int b = blockIdx.z;
    const float* Q = g_Q1 + (long)b * Ss * Hd;
    const float* K = g_K1 + (long)b * Ss * Hd;
    float* Pb = P + (long)b * Ss * Ss;
    const int m0 = blockIdx.y * 64, n0 = blockIdx.x * 64;
    const int tid = threadIdx.x;
    const int tx = tid & 15, ty = tid >> 4;
    const int lr = tid >> 2, lc = (tid & 3) * 4;
    float acc[4][4] = {};

    for (int k0 = 0; k0 < Hd; k0 += 16) {
        float4 qv = *(const float4*)&Q[(long)(m0 + lr) * Hd + k0 + lc];
        float4 kv = *(const float4*)&K[(long)(n0 + lr) * Hd + k0 + lc];
        Qs[lc + 0][lr] = qv.x; Qs[lc + 1][lr] = qv.y; Qs[lc + 2][lr] = qv.z; Qs[lc + 3][lr] = qv.w;
        Ks[lc + 0][lr] = kv.x; Ks[lc + 1][lr] = kv.y; Ks[lc + 2][lr] = kv.z; Ks[lc + 3][lr] = kv.w;
        __syncthreads();
        #pragma unroll
        for (int k = 0; k < 16; k++) {
            float4 a4 = *(const float4*)&Qs[k][ty * 4];
            float4 b4 = *(const float4*)&Ks[k][tx * 4];
            float ar[4] = {a4.x, a4.y, a4.z, a4.w};
            float br[4] = {b4.x, b4.y, b4.z, b4.w};
            #pragma unroll
            for (int i = 0; i < 4; i++)
                #pragma unroll
                for (int j = 0; j < 4; j++)
                    acc[i][j] += ar[i] * br[j];
        }
        __syncthreads();
    }

    const float slope = slopes[1];
    #pragma unroll
    for (int i = 0; i < 4; i++) {
        const int q = m0 + ty * 4 + i;
        #pragma unroll
        for (int j = 0; j < 4; j++) {
            const int kk = n0 + tx * 4 + j;
            Pb[(long)q * Ss + kk] = acc[i][j] * 0.125f - slope * fabsf((float)(q - kk));
        }
    }
}

// ---------------------------------------------------------------------------
// In-place row softmax over 2048 columns. grid = (2048, Bb), 256 threads.
// ---------------------------------------------------------------------------
__global__ void softmax_kernel(float* __restrict__ P)
{
    float* r = P + (long)blockIdx.y * Ss * Ss + (long)blockIdx.x * Ss;
    const int tid = threadIdx.x;
    __shared__ float red[256];

    float vals[8];
    float m = -1e30f;
    #pragma unroll
    for (int i = 0; i < 8; i++) {
        vals[i] = r[tid + i * 256];
        m = fmaxf(m, vals[i]);
    }
    red[tid] = m;
    __syncthreads();
    for (int s = 128; s > 0; s >>= 1) {
        if (tid < s) red[tid] = fmaxf(red[tid], red[tid + s]);
        __syncthreads();
    }
    m = red[0];
    __syncthreads();

    float sum = 0.f;
    #pragma unroll
    for (int i = 0; i < 8; i++) {
        vals[i] = __expf(vals[i] - m);
        sum += vals[i];
    }
    red[tid] = sum;
    __syncthreads();
    for (int s = 128; s > 0; s >>= 1) {
        if (tid < s) red[tid] += red[tid + s];
        __syncthreads();
    }
    const float inv = 1.f / red[0];
    #pragma unroll
    for (int i = 0; i < 8; i++)
        r[tid + i * 256] = vals[i] * inv;
}

// ---------------------------------------------------------------------------
// attn[b,h,q,d] = sum_k P[b,q,k] * V[b,h,k,d]
// grid = (16 heads, 32 q-tiles, Bb). BM=64(q) x BN=64(d) x BK=16(k).
// ---------------------------------------------------------------------------
__global__ void gemm_pv(const float* __restrict__ P, const float* __restrict__ V,
                        float* __restrict__ O)
{
    __shared__ float As[16][64];   // [k][q]
    __shared__ float Bs[16][64];   // [k][d]
    const int b = blockIdx.z;
    const float* Pb = P + (long)b * Ss * Ss;
    const float* Vh = V + (long)b * Ss * Ee + (long)blockIdx.x * Ss * Hd;
    float* Oh = O + (long)b * Ss * Ee + (long)blockIdx.x * Ss * Hd;
    const int m0 = blockIdx.y * 64;
    const int tid = threadIdx.x;
    const int tx = tid & 15, ty = tid >> 4;
    const int lr = tid >> 2, lc = (tid & 3) * 4;     // P loader
    const int bkr = tid >> 4, bdc = (tid & 15) * 4;  // V loader (16 k-rows x 64 d)
    float acc[4][4] = {};

    for (int k0 = 0; k0 < Ss; k0 += 16) {
        float4 av = *(const float4*)&Pb[(long)(m0 + lr) * Ss + k0 + lc];
        As[lc + 0][lr] = av.x; As[lc + 1][lr] = av.y; As[lc + 2][lr] = av.z; As[lc + 3][lr] = av.w;
        *(float4*)&Bs[bkr][bdc] = *(const float4*)&Vh[(long)(k0 + bkr) * Hd + bdc];
        __syncthreads();
        #pragma unroll
        for (int k = 0; k < 16; k++) {
            float4 a4 = *(const float4*)&As[k][ty * 4];
            float4 b4 = *(const float4*)&Bs[k][tx * 4];
            float ar[4] = {a4.x, a4.y, a4.z, a4.w};
            float br[4] = {b4.x, b4.y, b4.z, b4.w};
            #pragma unroll
            for (int i = 0; i < 4; i++)
                #pragma unroll
                for (int j = 0; j < 4; j++)
                    acc[i][j] += ar[i] * br[j];
        }
        __syncthreads();
    }

    #pragma unroll
    for (int i = 0; i < 4; i++) {
        const int q = m0 + ty * 4 + i;
        #pragma unroll
        for (int j = 0; j < 4; j++)
            Oh[(long)q * Hd + tx * 4 + j] = acc[i][j];
    }
}

// ---------------------------------------------------------------------------
extern "C" void kernel_launch(void* const* d_in, const int* in_sizes, int n_in,
                              void* d_out, int out_size)
{
    const float* x      = (const float*)d_in[0];
    const float* Wq     = (const float*)d_in[1];
    const float* bq     = (const float*)d_in[2];
    const float* Wk     = (const float*)d_in[3];
    const float* bk     = (const float*)d_in[4];
    const float* Wv     = (const float*)d_in[5];
    const float* bv     = (const float*)d_in[6];
    const float* Wo     = (const float*)d_in[7];
    const float* bo     = (const float*)d_in[8];
    const float* slopes = (const float*)d_in[9];

    float* out = (float*)d_out;                 // (B, S, E)
    float* P   = out + (long)Bb * Ss * Ee;      // probs1 (B, 1, S, S), computed in place

    float *pQ1, *pK1, *pV, *pAttn;
    cudaGetSymbolAddress((void**)&pQ1, g_Q1);
    cudaGetSymbolAddress((void**)&pK1, g_K1);
    cudaGetSymbolAddress((void**)&pV, g_V);
    cudaGetSymbolAddress((void**)&pAttn, g_attn);

    // Head-1 Q/K projections: only x rows 128..255 per batch are needed.
    gemm_nt<<<dim3(Ee / 64, 128 / 64, Bb), 256>>>(x + 128 * Ee, Wq, bq, pQ1,
                                                  128, Ee, Ee, (long)Ss * Ee, (long)128 * Ee);
    gemm_nt<<<dim3(Ee / 64, 128 / 64, Bb), 256>>>(x + 128 * Ee, Wk, bk, pK1,
                                                  128, Ee, Ee, (long)Ss * Ee, (long)128 * Ee);
    // Full V projection.
    gemm_nt<<<dim3(Ee / 64, Ss / 64, Bb), 256>>>(x, Wv, bv, pV,
                                                 Ss, Ee, Ee, (long)Ss * Ee, (long)Ss * Ee);
    // Head-1 scores + ALiBi, then softmax in place (directly into d_out probs region).
    scores_kernel<<<dim3(Ss / 64, Ss / 64, Bb), 256>>>(slopes, P);
    softmax_kernel<<<dim3(Ss, Bb), 256>>>(P);
    // attn = probs1 @ V (all heads share head-1 probs).
    gemm_pv<<<dim3(Hh, Ss / 64, Bb), 256>>>(P, pV, pAttn);
    // Output projection.
    gemm_nt<<<dim3(Ee / 64, Ss / 64, Bb), 256>>>(pAttn, Wo, bo, out,
                                                 Ss, Ee, Ee, (long)Ss * Ee, (long)Ss * Ee);
}

// round 6
// speedup vs baseline: 1.3638x; 1.3638x over previous
#include <cuda_runtime.h>
#include <cuda_bf16.h>
#include <mma.h>
#include <cstdint>

using namespace nvcuda;

#define Bb 2
#define Ss 2048
#define Ee 1024
#define Hh 16
#define Hd 64

// Scratch (allocation-free rule: __device__ globals) — round-1 proven set.
__device__ float g_Q1[Bb * Ss * Hd];
__device__ float g_K1[Bb * Ss * Hd];
__device__ float g_V [Bb * Ss * Ee];
__device__ float g_attn[Bb * Ss * Ee];

// ---------------------------------------------------------------------------
// wmma split-bf16 NT GEMM: C[m,n] = sum_k A[m,k] * B[n,k] + bias[n]
// A: (M,K) fp32 row-major (per-z stride Az). B: (N,K) fp32 row-major (shared).
// In-kernel split: A = Ah + Al (bf16), product = Ah*Bh + Ah*Bl + Al*Bh.
// BM=BN=64, BK=32, 256 threads (8 warps: 2 m-halves x 4 n-quarters),
// 2 fragments (16x16) per warp. Conservative: no pipelining, scalar stores.
// ---------------------------------------------------------------------------
__global__ void __launch_bounds__(256) wsplit_gemm(
    const float* __restrict__ A, long Az,
    const float* __restrict__ B,
    float* __restrict__ C, long Cz, int ldC,
    const float* __restrict__ bias, int K)
{
    __shared__ __align__(128) __nv_bfloat16 sAh[64][40];
    __shared__ __align__(128) __nv_bfloat16 sAl[64][40];
    __shared__ __align__(128) __nv_bfloat16 sBh[64][40];
    __shared__ __align__(128) __nv_bfloat16 sBl[64][40];
    __shared__ __align__(128) float sC[64][72];

    const int tid = threadIdx.x, wid = tid >> 5;
    const int wm = wid & 1, wn = wid >> 1;
    const int m0 = blockIdx.y * 64, n0 = blockIdx.x * 64;
    A += (size_t)blockIdx.z * Az;
    C += (size_t)blockIdx.z * Cz;

    // Loader map: 256 threads cover 64 rows x 32 cols (8 cols per thread).
    const int lrow = tid >> 2, lcb = (tid & 3) * 8;

    wmma::fragment<wmma::accumulator, 16, 16, 16, float> acc[2];
    wmma::fill_fragment(acc[0], 0.0f);
    wmma::fill_fragment(acc[1], 0.0f);

    for (int k0 = 0; k0 < K; k0 += 32) {
        const float* ga = A + (size_t)(m0 + lrow) * K + k0 + lcb;
        const float* gb = B + (size_t)(n0 + lrow) * K + k0 + lcb;
        #pragma unroll
        for (int j = 0; j < 8; j += 4) {
            float4 va = *(const float4*)(ga + j);
            float4 vb = *(const float4*)(gb + j);
            float av[4] = {va.x, va.y, va.z, va.w};
            float bv[4] = {vb.x, vb.y, vb.z, vb.w};
            #pragma unroll
            for (int u = 0; u < 4; ++u) {
                __nv_bfloat16 ha = __float2bfloat16(av[u]);
                sAh[lrow][lcb + j + u] = ha;
                sAl[lrow][lcb + j + u] = __float2bfloat16(av[u] - __bfloat162float(ha));
                __nv_bfloat16 hb = __float2bfloat16(bv[u]);
                sBh[lrow][lcb + j + u] = hb;
                sBl[lrow][lcb + j + u] = __float2bfloat16(bv[u] - __bfloat162float(hb));
            }
        }
        __syncthreads();

        #pragma unroll
        for (int p = 0; p < 3; ++p) {
            const __nv_bfloat16 (*aS)[40] = (p == 2) ? sAl : sAh;
            const __nv_bfloat16 (*bS)[40] = (p == 1) ? sBl : sBh;
            #pragma unroll
            for (int kk = 0; kk < 32; kk += 16) {
                wmma::fragment<wmma::matrix_a, 16, 16, 16, __nv_bfloat16, wmma::row_major> af;
                wmma::fragment<wmma::matrix_b, 16, 16, 16, __nv_bfloat16, wmma::col_major> bf;
                wmma::load_matrix_sync(bf, &bS[wn * 16][kk], 40);
                #pragma unroll
                for (int i = 0; i < 2; ++i) {
                    wmma::load_matrix_sync(af, &aS[wm * 32 + i * 16][kk], 40);
                    wmma::mma_sync(acc[i], af, bf, acc[i]);
                }
            }
        }
        __syncthreads();
    }

    wmma::store_matrix_sync(&sC[wm * 32][wn * 16], acc[0], 72, wmma::mem_row_major);
    wmma::store_matrix_sync(&sC[wm * 32 + 16][wn * 16], acc[1], 72, wmma::mem_row_major);
    __syncthreads();

    // Scalar, coalesced epilogue (round-1 proven store style).
    #pragma unroll
    for (int it = 0; it < 16; ++it) {
        int idx = it * 256 + tid;
        int r = idx >> 6, c = idx & 63;
        float v = sC[r][c];
        if (bias) v += bias[n0 + c];
        C[(size_t)(m0 + r) * ldC + n0 + c] = v;
    }
}

// ---------------------------------------------------------------------------
// Round-1 proven kernels, verbatim: scores, softmax, PV GEMM.
// ---------------------------------------------------------------------------
__global__ void scores_kernel(const float* __restrict__ slopes, float* __restrict__ P)
{
    __shared__ float Qs[16][64];
    __shared__ float Ks[16][64];
    const int b = blockIdx.z;
    const float* Q = g_Q1 + (long)b * Ss * Hd;
    const float* K = g_K1 + (long)b * Ss * Hd;
    float* Pb = P + (long)b * Ss * Ss;
    const int m0 = blockIdx.y * 64, n0 = blockIdx.x * 64;
    const int tid = threadIdx.x;
    const int tx = tid & 15, ty = tid >> 4;
    const int lr = tid >> 2, lc = (tid & 3) * 4;
    float acc[4][4] = {};

    for (int k0 = 0; k0 < Hd; k0 += 16) {
        float4 qv = *(const float4*)&Q[(long)(m0 + lr) * Hd + k0 + lc];
        float4 kv = *(const float4*)&K[(long)(n0 + lr) * Hd + k0 + lc];
        Qs[lc + 0][lr] = qv.x; Qs[lc + 1][lr] = qv.y; Qs[lc + 2][lr] = qv.z; Qs[lc + 3][lr] = qv.w;
        Ks[lc + 0][lr] = kv.x; Ks[lc + 1][lr] = kv.y; Ks[lc + 2][lr] = kv.z; Ks[lc + 3][lr] = kv.w;
        __syncthreads();
        #pragma unroll
        for (int k = 0; k < 16; k++) {
            float4 a4 = *(const float4*)&Qs[k][ty * 4];
            float4 b4 = *(const float4*)&Ks[k][tx * 4];
            float ar[4] = {a4.x, a4.y, a4.z, a4.w};
            float br[4] = {b4.x, b4.y, b4.z, b4.w};
            #pragma unroll
            for (int i = 0; i < 4; i++)
                #pragma unroll
                for (int j = 0; j < 4; j++)
                    acc[i][j] += ar[i] * br[j];
        }
        __syncthreads();
    }

    const float slope = slopes[1];
    #pragma unroll
    for (int i = 0; i < 4; i++) {
        const int q = m0 + ty * 4 + i;
        #pragma unroll
        for (int j = 0; j < 4; j++) {
            const int kk = n0 + tx * 4 + j;
            Pb[(long)q * Ss + kk] = acc[i][j] * 0.125f - slope * fabsf((float)(q - kk));
        }
    }
}

__global__ void softmax_kernel(float* __restrict__ P)
{
    float* r = P + (long)blockIdx.y * Ss * Ss + (long)blockIdx.x * Ss;
    const int tid = threadIdx.x;
    __shared__ float red[256];

    float vals[8];
    float m = -1e30f;
    #pragma unroll
    for (int i = 0; i < 8; i++) {
        vals[i] = r[tid + i * 256];
        m = fmaxf(m, vals[i]);
    }
    red[tid] = m;
    __syncthreads();
    for (int s = 128; s > 0; s >>= 1) {
        if (tid < s) red[tid] = fmaxf(red[tid], red[tid + s]);
        __syncthreads();
    }
    m = red[0];
    __syncthreads();

    float sum = 0.f;
    #pragma unroll
    for (int i = 0; i < 8; i++) {
        vals[i] = __expf(vals[i] - m);
        sum += vals[i];
    }
    red[tid] = sum;
    __syncthreads();
    for (int s = 128; s > 0; s >>= 1) {
        if (tid < s) red[tid] += red[tid + s];
        __syncthreads();
    }
    const float inv = 1.f / red[0];
    #pragma unroll
    for (int i = 0; i < 8; i++)
        r[tid + i * 256] = vals[i] * inv;
}

__global__ void gemm_pv(const float* __restrict__ P, const float* __restrict__ V,
                        float* __restrict__ O)
{
    __shared__ float As[16][64];   // [k][q]
    __shared__ float Bs[16][64];   // [k][d]
    const int b = blockIdx.z;
    const float* Pb = P + (long)b * Ss * Ss;
    const float* Vh = V + (long)b * Ss * Ee + (long)blockIdx.x * Ss * Hd;
    float* Oh = O + (long)b * Ss * Ee + (long)blockIdx.x * Ss * Hd;
    const int m0 = blockIdx.y * 64;
    const int tid = threadIdx.x;
    const int tx = tid & 15, ty = tid >> 4;
    const int lr = tid >> 2, lc = (tid & 3) * 4;     // P loader
    const int bkr = tid >> 4, bdc = (tid & 15) * 4;  // V loader (16 k-rows x 64 d)
    float acc[4][4] = {};

    for (int k0 = 0; k0 < Ss; k0 += 16) {
        float4 av = *(const float4*)&Pb[(long)(m0 + lr) * Ss + k0 + lc];
        As[lc + 0][lr] = av.x; As[lc + 1][lr] = av.y; As[lc + 2][lr] = av.z; As[lc + 3][lr] = av.w;
        *(float4*)&Bs[bkr][bdc] = *(const float4*)&Vh[(long)(k0 + bkr) * Hd + bdc];
        __syncthreads();
        #pragma unroll
        for (int k = 0; k < 16; k++) {
            float4 a4 = *(const float4*)&As[k][ty * 4];
            float4 b4 = *(const float4*)&Bs[k][tx * 4];
            float ar[4] = {a4.x, a4.y, a4.z, a4.w};
            float br[4] = {b4.x, b4.y, b4.z, b4.w};
            #pragma unroll
            for (int i = 0; i < 4; i++)
                #pragma unroll
                for (int j = 0; j < 4; j++)
                    acc[i][j] += ar[i] * br[j];
        }
        __syncthreads();
    }

    #pragma unroll
    for (int i = 0; i < 4; i++) {
        const int q = m0 + ty * 4 + i;
        #pragma unroll
        for (int j = 0; j < 4; j++)
            Oh[(long)q * Hd + tx * 4 + j] = acc[i][j];
    }
}

// ---------------------------------------------------------------------------
extern "C" void kernel_launch(void* const* d_in, const int* in_sizes, int n_in,
                              void* d_out, int out_size)
{
    const float* x      = (const float*)d_in[0];
    const float* Wq     = (const float*)d_in[1];
    const float* bq     = (const float*)d_in[2];
    const float* Wk     = (const float*)d_in[3];
    const float* bk     = (const float*)d_in[4];
    const float* Wv     = (const float*)d_in[5];
    const float* bv     = (const float*)d_in[6];
    const float* Wo     = (const float*)d_in[7];
    const float* bo     = (const float*)d_in[8];
    const float* slopes = (const float*)d_in[9];

    float* out = (float*)d_out;                 // (B, S, E)
    float* P   = out + (long)Bb * Ss * Ee;      // probs1 (B, 1, S, S), computed in place

    float *pQ1, *pK1, *pV, *pAttn;
    cudaGetSymbolAddress((void**)&pQ1, g_Q1);
    cudaGetSymbolAddress((void**)&pK1, g_K1);
    cudaGetSymbolAddress((void**)&pV, g_V);
    cudaGetSymbolAddress((void**)&pAttn, g_attn);

    // Head-1 Q/K projections: rows 128..255 per batch of x @ W^T (wmma split-bf16).
    wsplit_gemm<<<dim3(Ee / 64, 128 / 64, Bb), 256>>>(
        x + 128 * Ee, (long)Ss * Ee, Wq, pQ1, (long)128 * Ee, Ee, bq, Ee);
    wsplit_gemm<<<dim3(Ee / 64, 128 / 64, Bb), 256>>>(
        x + 128 * Ee, (long)Ss * Ee, Wk, pK1, (long)128 * Ee, Ee, bk, Ee);
    // Full V projection (flatten batches: M = 4096).
    wsplit_gemm<<<dim3(Ee / 64, Bb * Ss / 64, 1), 256>>>(
        x, 0, Wv, pV, 0, Ee, bv, Ee);

    // Head-1 scores + ALiBi, then softmax in place (directly into d_out probs region).
    scores_kernel<<<dim3(Ss / 64, Ss / 64, Bb), 256>>>(slopes, P);
    softmax_kernel<<<dim3(Ss, Bb), 256>>>(P);

    // attn = probs1 @ V (all heads share head-1 probs) — proven SIMT kernel.
    gemm_pv<<<dim3(Hh, Ss / 64, Bb), 256>>>(P, pV, pAttn);

    // Output projection: attn_out.reshape(B*S, E) @ Wo^T (wmma split-bf16).
    wsplit_gemm<<<dim3(Ee / 64, Bb * Ss / 64, 1), 256>>>(
        pAttn, 0, Wo, out, 0, Ee, bo, Ee);
}

// round 10
// speedup vs baseline: 1.7537x; 1.2859x over previous
#include <cuda_runtime.h>
#include <cuda_bf16.h>
#include <mma.h>
#include <cstdint>

using namespace nvcuda;

#define Bb 2
#define Ss 2048
#define Ee 1024
#define Hh 16
#define Hd 64

// Scratch (allocation-free rule: __device__ globals)
__device__ float g_Q1[Bb * Ss * Hd];
__device__ float g_K1[Bb * Ss * Hd];
__device__ float g_V [Bb * Ss * Ee];     // V projection, flat (b, s, e) == (b, h, k, d) chunks
__device__ float g_Vt[Bb * Ee * Ss];     // Vt[b][h*64+d][k] = V[b, h, k, d]
__device__ float g_R [Bb * Ss * Ee];     // PV result, row-major (b, q, n) with n = h*64+d
__device__ float g_attn[Bb * Ss * Ee];   // attn in flat (b, h, q, d) layout

// ---------------------------------------------------------------------------
// wmma split-bf16 NT GEMM (VALIDATED round 6; Bz batch stride added round 9):
// C[m,n] = sum_k A[m,k]*B[n,k] + bias[n]
// ---------------------------------------------------------------------------
__global__ void __launch_bounds__(256) wsplit_gemm(
    const float* __restrict__ A, long Az,
    const float* __restrict__ B, long Bz,
    float* __restrict__ C, long Cz, int ldC,
    const float* __restrict__ bias, int K)
{
    __shared__ __align__(128) __nv_bfloat16 sAh[64][40];
    __shared__ __align__(128) __nv_bfloat16 sAl[64][40];
    __shared__ __align__(128) __nv_bfloat16 sBh[64][40];
    __shared__ __align__(128) __nv_bfloat16 sBl[64][40];
    __shared__ __align__(128) float sC[64][72];

    const int tid = threadIdx.x, wid = tid >> 5;
    const int wm = wid & 1, wn = wid >> 1;
    const int m0 = blockIdx.y * 64, n0 = blockIdx.x * 64;
    A += (size_t)blockIdx.z * Az;
    B += (size_t)blockIdx.z * Bz;
    C += (size_t)blockIdx.z * Cz;

    const int lrow = tid >> 2, lcb = (tid & 3) * 8;

    wmma::fragment<wmma::accumulator, 16, 16, 16, float> acc[2];
    wmma::fill_fragment(acc[0], 0.0f);
    wmma::fill_fragment(acc[1], 0.0f);

    for (int k0 = 0; k0 < K; k0 += 32) {
        const float* ga = A + (size_t)(m0 + lrow) * K + k0 + lcb;
        const float* gb = B + (size_t)(n0 + lrow) * K + k0 + lcb;
        #pragma unroll
        for (int j = 0; j < 8; j += 4) {
            float4 va = *(const float4*)(ga + j);
            float4 vb = *(const float4*)(gb + j);
            float av[4] = {va.x, va.y, va.z, va.w};
            float bv[4] = {vb.x, vb.y, vb.z, vb.w};
            #pragma unroll
            for (int u = 0; u < 4; ++u) {
                __nv_bfloat16 ha = __float2bfloat16(av[u]);
                sAh[lrow][lcb + j + u] = ha;
                sAl[lrow][lcb + j + u] = __float2bfloat16(av[u] - __bfloat162float(ha));
                __nv_bfloat16 hb = __float2bfloat16(bv[u]);
                sBh[lrow][lcb + j + u] = hb;
                sBl[lrow][lcb + j + u] = __float2bfloat16(bv[u] - __bfloat162float(hb));
            }
        }
        __syncthreads();

        #pragma unroll
        for (int p = 0; p < 3; ++p) {
            const __nv_bfloat16 (*aS)[40] = (p == 2) ? sAl : sAh;
            const __nv_bfloat16 (*bS)[40] = (p == 1) ? sBl : sBh;
            #pragma unroll
            for (int kk = 0; kk < 32; kk += 16) {
                wmma::fragment<wmma::matrix_a, 16, 16, 16, __nv_bfloat16, wmma::row_major> af;
                wmma::fragment<wmma::matrix_b, 16, 16, 16, __nv_bfloat16, wmma::col_major> bf;
                wmma::load_matrix_sync(bf, &bS[wn * 16][kk], 40);
                #pragma unroll
                for (int i = 0; i < 2; ++i) {
                    wmma::load_matrix_sync(af, &aS[wm * 32 + i * 16][kk], 40);
                    wmma::mma_sync(acc[i], af, bf, acc[i]);
                }
            }
        }
        __syncthreads();
    }

    wmma::store_matrix_sync(&sC[wm * 32][wn * 16], acc[0], 72, wmma::mem_row_major);
    wmma::store_matrix_sync(&sC[wm * 32 + 16][wn * 16], acc[1], 72, wmma::mem_row_major);
    __syncthreads();

    #pragma unroll
    for (int it = 0; it < 16; ++it) {
        int idx = it * 256 + tid;
        int r = idx >> 6, c = idx & 63;
        float v = sC[r][c];
        if (bias) v += bias[n0 + c];
        C[(size_t)(m0 + r) * ldC + n0 + c] = v;
    }
}

// ---------------------------------------------------------------------------
// Head-aware V transpose (THE FIX): the reference reshape makes head h a
// CONTIGUOUS chunk of the flat projection: V[b,h,k,d] = Vflat[b][h*Ss*Hd + k*Hd + d].
// Build Vt[b][h*64+d][k] = V[b,h,k,d] so PV is a pure NT GEMM.
// grid (Ss/32, Hd/32, Bb*Hh), block (32, 8).
// ---------------------------------------------------------------------------
__global__ void transpose_vh(const float* __restrict__ in, float* __restrict__ outT)
{
    __shared__ float t[32][33];
    const int b = blockIdx.z >> 4, h = blockIdx.z & 15;
    const int k0 = blockIdx.x * 32, d0 = blockIdx.y * 32;
    const int tx = threadIdx.x, ty = threadIdx.y;
    const float* src = in + (size_t)b * Ss * Ee + (size_t)h * Ss * Hd;  // (k, d), ld = Hd
    float* dst = outT + (size_t)b * Ee * Ss + (size_t)h * Hd * Ss;      // (d, k), ld = Ss
    #pragma unroll
    for (int i = 0; i < 32; i += 8)
        t[ty + i][tx] = src[(size_t)(k0 + ty + i) * Hd + d0 + tx];
    __syncthreads();
    #pragma unroll
    for (int i = 0; i < 32; i += 8)
        dst[(size_t)(d0 + ty + i) * Ss + k0 + tx] = t[tx][ty + i];
}

// ---------------------------------------------------------------------------
// Permute PV result R (b, q, n) row-major into flat (b, h, q, d) layout:
// attn[b*Ss*Ee + (n>>6)*Ss*Hd + q*Hd + (n&63)] = R[b*Ss*Ee + q*Ee + n]
// ---------------------------------------------------------------------------
__global__ void permute_attn(const float* __restrict__ R, float* __restrict__ A)
{
    const int idx = blockIdx.x * 256 + threadIdx.x;   // 0 .. Bb*Ss*Ee-1
    const int e = idx & (Ee - 1);
    const int q = (idx >> 10) & (Ss - 1);
    const int b = idx >> 21;
    A[(size_t)b * Ss * Ee + (size_t)(e >> 6) * (Ss * Hd) + (size_t)q * Hd + (e & 63)] = R[idx];
}

// ------------------------- scores + softmax (round-1 proven) -----------------
__global__ void scores_kernel(const float* __restrict__ slopes, float* __restrict__ P)
{
    __shared__ float Qs[16][64];
    __shared__ float Ks[16][64];
    const int b = blockIdx.z;
    const float* Q = g_Q1 + (long)b * Ss * Hd;
    const float* K = g_K1 + (long)b * Ss * Hd;
    float* Pb = P + (long)b * Ss * Ss;
    const int m0 = blockIdx.y * 64, n0 = blockIdx.x * 64;
    const int tid = threadIdx.x;
    const int tx = tid & 15, ty = tid >> 4;
    const int lr = tid >> 2, lc = (tid & 3) * 4;
    float acc[4][4] = {};

    for (int k0 = 0; k0 < Hd; k0 += 16) {
        float4 qv = *(const float4*)&Q[(long)(m0 + lr) * Hd + k0 + lc];
        float4 kv = *(const float4*)&K[(long)(n0 + lr) * Hd + k0 + lc];
        Qs[lc + 0][lr] = qv.x; Qs[lc + 1][lr] = qv.y; Qs[lc + 2][lr] = qv.z; Qs[lc + 3][lr] = qv.w;
        Ks[lc + 0][lr] = kv.x; Ks[lc + 1][lr] = kv.y; Ks[lc + 2][lr] = kv.z; Ks[lc + 3][lr] = kv.w;
        __syncthreads();
        #pragma unroll
        for (int k = 0; k < 16; k++) {
            float4 a4 = *(const float4*)&Qs[k][ty * 4];
            float4 b4 = *(const float4*)&Ks[k][tx * 4];
            float ar[4] = {a4.x, a4.y, a4.z, a4.w};
            float br[4] = {b4.x, b4.y, b4.z, b4.w};
            #pragma unroll
            for (int i = 0; i < 4; i++)
                #pragma unroll
                for (int j = 0; j < 4; j++)
                    acc[i][j] += ar[i] * br[j];
        }
        __syncthreads();
    }

    const float slope = slopes[1];
    #pragma unroll
    for (int i = 0; i < 4; i++) {
        const int q = m0 + ty * 4 + i;
        #pragma unroll
        for (int j = 0; j < 4; j++) {
            const int kk = n0 + tx * 4 + j;
            Pb[(long)q * Ss + kk] = acc[i][j] * 0.125f - slope * fabsf((float)(q - kk));
        }
    }
}

__global__ void softmax_kernel(float* __restrict__ P)
{
    float* r = P + (long)blockIdx.y * Ss * Ss + (long)blockIdx.x * Ss;
    const int tid = threadIdx.x;
    __shared__ float red[256];

    float vals[8];
    float m = -1e30f;
    #pragma unroll
    for (int i = 0; i < 8; i++) {
        vals[i] = r[tid + i * 256];
        m = fmaxf(m, vals[i]);
    }
    red[tid] = m;
    __syncthreads();
    for (int s = 128; s > 0; s >>= 1) {
        if (tid < s) red[tid] = fmaxf(red[tid], red[tid + s]);
        __syncthreads();
    }
    m = red[0];
    __syncthreads();

    float sum = 0.f;
    #pragma unroll
    for (int i = 0; i < 8; i++) {
        vals[i] = __expf(vals[i] - m);
        sum += vals[i];
    }
    red[tid] = sum;
    __syncthreads();
    for (int s = 128; s > 0; s >>= 1) {
        if (tid < s) red[tid] += red[tid + s];
        __syncthreads();
    }
    const float inv = 1.f / red[0];
    #pragma unroll
    for (int i = 0; i < 8; i++)
        r[tid + i * 256] = vals[i] * inv;
}

// ---------------------------------------------------------------------------
extern "C" void kernel_launch(void* const* d_in, const int* in_sizes, int n_in,
                              void* d_out, int out_size)
{
    const float* x      = (const float*)d_in[0];
    const float* Wq     = (const float*)d_in[1];
    const float* bq     = (const float*)d_in[2];
    const float* Wk     = (const float*)d_in[3];
    const float* bk     = (const float*)d_in[4];
    const float* Wv     = (const float*)d_in[5];
    const float* bv     = (const float*)d_in[6];
    const float* Wo     = (const float*)d_in[7];
    const float* bo     = (const float*)d_in[8];
    const float* slopes = (const float*)d_in[9];

    float* out = (float*)d_out;                 // (B, S, E)
    float* P   = out + (long)Bb * Ss * Ee;      // probs1 (B, 1, S, S), computed in place

    float *pQ1, *pK1, *pV, *pVt, *pR, *pAttn;
    cudaGetSymbolAddress((void**)&pQ1, g_Q1);
    cudaGetSymbolAddress((void**)&pK1, g_K1);
    cudaGetSymbolAddress((void**)&pV, g_V);
    cudaGetSymbolAddress((void**)&pVt, g_Vt);
    cudaGetSymbolAddress((void**)&pR, g_R);
    cudaGetSymbolAddress((void**)&pAttn, g_attn);

    // Head-1 Q/K projections: rows 128..255 per batch of x @ W^T (validated wmma).
    wsplit_gemm<<<dim3(Ee / 64, 128 / 64, Bb), 256>>>(
        x + 128 * Ee, (long)Ss * Ee, Wq, 0, pQ1, (long)128 * Ee, Ee, bq, Ee);
    wsplit_gemm<<<dim3(Ee / 64, 128 / 64, Bb), 256>>>(
        x + 128 * Ee, (long)Ss * Ee, Wk, 0, pK1, (long)128 * Ee, Ee, bk, Ee);
    // Full V projection (flatten batches: M = 4096).
    wsplit_gemm<<<dim3(Ee / 64, Bb * Ss / 64, 1), 256>>>(
        x, 0, Wv, 0, pV, 0, Ee, bv, Ee);

    // Head-1 scores + ALiBi (proven SIMT), then softmax in place.
    scores_kernel<<<dim3(Ss / 64, Ss / 64, Bb), 256>>>(slopes, P);
    softmax_kernel<<<dim3(Ss, Bb), 256>>>(P);

    // Head-aware transpose (contiguous-reshape semantics), then PV on the
    // VALIDATED NT GEMM: R[b,q,n] = sum_k P[b,q,k] * Vt[b,n,k], K = Ss.
    transpose_vh<<<dim3(Ss / 32, Hd / 32, Bb * Hh), dim3(32, 8)>>>(pV, pVt);
    wsplit_gemm<<<dim3(Ee / 64, Ss / 64, Bb), 256>>>(
        P, (long)Ss * Ss, pVt, (long)Ee * Ss, pR, (long)Ss * Ee, Ee, nullptr, Ss);

    // Permute row-major R into flat (b, h, q, d) layout (reshape semantics).
    permute_attn<<<Bb * Ss * Ee / 256, 256>>>(pR, pAttn);

    // Output projection: attn_out.reshape(B*S, E) @ Wo^T (validated wmma).
    wsplit_gemm<<<dim3(Ee / 64, Bb * Ss / 64, 1), 256>>>(
        pAttn, 0, Wo, 0, out, 0, Ee, bo, Ee);
}